// round 1
// baseline (speedup 1.0000x reference)
#include <cuda_runtime.h>
#include <cuda_bf16.h>

// ----------------------------------------------------------------------------
// VectorQuantizerEMAKeras: fused distance-GEMM + argmin + gather + loss
//
// inputs : d_in[0] = X  [N=262144, D=128] fp32   (B,H,W,D flattened)
//          d_in[1] = E  [D=128, K=1024]   fp32
// outputs: d_out   = [ quantized (N*D) | loss (1) | indices-as-float (N) ]
// ----------------------------------------------------------------------------

#define DDIM   128
#define MTILE  128
#define NTILE  128
#define THREADS 256
#define XS_STRIDE 132   // padded row stride in floats (multiple of 4 for float4)

// scratch (no cudaMalloc allowed)
__device__ double g_loss_acc;
__device__ float  g_esq[8192];

// --- prep: zero loss accumulator, compute ||e_k||^2 ---------------------------
__global__ void vq_prep_kernel(const float* __restrict__ E, int K) {
    int k = blockIdx.x * blockDim.x + threadIdx.x;
    if (k == 0) g_loss_acc = 0.0;
    if (k < K) {
        float s = 0.f;
#pragma unroll 8
        for (int d = 0; d < DDIM; ++d) {
            float e = E[(size_t)d * K + k];
            s = fmaf(e, e, s);
        }
        g_esq[k] = s;
    }
}

// --- main fused kernel --------------------------------------------------------
__global__ __launch_bounds__(THREADS) void vq_main_kernel(
    const float* __restrict__ X, const float* __restrict__ E,
    float* __restrict__ q_out, float* __restrict__ idx_out, int K)
{
    extern __shared__ float smem[];
    float* Xs    = smem;                               // [128][XS_STRIDE] d-major
    float* Es    = smem + DDIM * XS_STRIDE;            // [128][XS_STRIDE] d-major
    float* xsq_s = smem + 2 * DDIM * XS_STRIDE;        // [128]
    int*   idx_s = (int*)(xsq_s + MTILE);              // [128]
    // reduction buffers alias Es (only used after the chunk loop)
    float* red_val = Es;                               // [128*16]
    int*   red_idx = (int*)(Es + MTILE * 16);          // [128*16]

    const int t = threadIdx.x;
    const int rowBase = blockIdx.x * MTILE;

    // ---- load X tile, transposed into SMEM (coalesced 128B global reads) ----
    const float4* X4 = (const float4*)(X + (size_t)rowBase * DDIM);
#pragma unroll
    for (int i = 0; i < (MTILE * DDIM / 4) / THREADS; ++i) {   // 16 iters
        int idx = t + i * THREADS;
        int row = idx >> 5;          // /32 float4s per row
        int c4  = idx & 31;
        float4 v = X4[row * 32 + c4];
        int d = c4 * 4;
        Xs[(d + 0) * XS_STRIDE + row] = v.x;
        Xs[(d + 1) * XS_STRIDE + row] = v.y;
        Xs[(d + 2) * XS_STRIDE + row] = v.z;
        Xs[(d + 3) * XS_STRIDE + row] = v.w;
    }
    __syncthreads();

    // ---- per-row ||x||^2 ----
    if (t < MTILE) {
        float s = 0.f;
#pragma unroll 8
        for (int d = 0; d < DDIM; ++d) {
            float x = Xs[d * XS_STRIDE + t];
            s = fmaf(x, x, s);
        }
        xsq_s[t] = s;
    }
    __syncthreads();

    const int tx = t & 15, ty = t >> 4;
    const int r0 = ty * 8, kt0 = tx * 8;

    float xs[8];
#pragma unroll
    for (int j = 0; j < 8; ++j) xs[j] = xsq_s[r0 + j];

    float minv[8]; int mini[8];
#pragma unroll
    for (int j = 0; j < 8; ++j) { minv[j] = 3.402823466e38f; mini[j] = 0; }

    // ---- chunk loop over codebook, 128 codes at a time ----
    for (int c0 = 0; c0 < K; c0 += NTILE) {
        __syncthreads();   // previous chunk's compute done before overwriting Es
        // load E chunk [128d x 128k] (coalesced: k contiguous in global)
#pragma unroll
        for (int i = 0; i < (DDIM * NTILE / 4) / THREADS; ++i) {  // 16 iters
            int idx = t + i * THREADS;
            int d  = idx >> 5;
            int k4 = idx & 31;
            const float4* Er = (const float4*)(E + (size_t)d * K + c0);
            float4 v = Er[k4];
            float* dst = &Es[d * XS_STRIDE + k4 * 4];
            dst[0] = v.x; dst[1] = v.y; dst[2] = v.z; dst[3] = v.w;
        }
        __syncthreads();

        float acc[8][8];
#pragma unroll
        for (int j = 0; j < 8; ++j)
#pragma unroll
            for (int jj = 0; jj < 8; ++jj) acc[j][jj] = 0.f;

#pragma unroll 8
        for (int d = 0; d < DDIM; ++d) {
            float4 a0 = *(const float4*)&Xs[d * XS_STRIDE + r0];
            float4 a1 = *(const float4*)&Xs[d * XS_STRIDE + r0 + 4];
            float4 b0 = *(const float4*)&Es[d * XS_STRIDE + kt0];
            float4 b1 = *(const float4*)&Es[d * XS_STRIDE + kt0 + 4];
            float a[8] = {a0.x, a0.y, a0.z, a0.w, a1.x, a1.y, a1.z, a1.w};
            float b[8] = {b0.x, b0.y, b0.z, b0.w, b1.x, b1.y, b1.z, b1.w};
#pragma unroll
            for (int j = 0; j < 8; ++j)
#pragma unroll
                for (int jj = 0; jj < 8; ++jj)
                    acc[j][jj] = fmaf(a[j], b[jj], acc[j][jj]);
        }

        // fold into running min; replicate reference rounding:
        // dist = fl( fl(xsq - fl(2*c)) + esq )
#pragma unroll
        for (int jj = 0; jj < 8; ++jj) {
            float esq = __ldg(&g_esq[c0 + kt0 + jj]);
            int   kidx = c0 + kt0 + jj;
#pragma unroll
            for (int j = 0; j < 8; ++j) {
                float m    = __fmul_rn(2.0f, acc[j][jj]);
                float tt   = __fadd_rn(xs[j], -m);
                float dist = __fadd_rn(tt, esq);
                if (dist < minv[j]) { minv[j] = dist; mini[j] = kidx; }
            }
        }
    }

    // ---- cross-thread argmin reduction (16 threads per row) ----
    __syncthreads();   // all FMA reads of Es finished; safe to alias
#pragma unroll
    for (int j = 0; j < 8; ++j) {
        red_val[(r0 + j) * 16 + tx] = minv[j];
        red_idx[(r0 + j) * 16 + tx] = mini[j];
    }
    __syncthreads();
    if (t < MTILE) {
        float bv = red_val[t * 16];
        int   bi = red_idx[t * 16];
#pragma unroll
        for (int s = 1; s < 16; ++s) {
            float v = red_val[t * 16 + s];
            int   i = red_idx[t * 16 + s];
            if (v < bv || (v == bv && i < bi)) { bv = v; bi = i; }
        }
        idx_s[t] = bi;
        idx_out[rowBase + t] = (float)bi;
    }
    __syncthreads();

    // ---- gather winning codebook column, write quantized, accumulate loss ----
    float lsum = 0.f;
    const int half = t >> 7;       // 0/1
    const int d    = t & 127;
    for (int rr = 0; rr < MTILE; rr += 2) {
        int row = rr + half;
        int bi  = idx_s[row];
        float e = __ldg(&E[(size_t)d * K + bi]);   // L2-resident
        float x = Xs[d * XS_STRIDE + row];
        q_out[(size_t)(rowBase + row) * DDIM + d] = e;
        float df = e - x;
        lsum = fmaf(df, df, lsum);
    }

    // block reduce loss -> one double atomic per CTA (deterministic to ~1e-13)
#pragma unroll
    for (int o = 16; o > 0; o >>= 1)
        lsum += __shfl_xor_sync(0xffffffffu, lsum, o);
    __syncthreads();
    float* rbuf = smem;   // Xs no longer needed
    if ((t & 31) == 0) rbuf[t >> 5] = lsum;
    __syncthreads();
    if (t == 0) {
        double s = 0.0;
        for (int w = 0; w < THREADS / 32; ++w) s += (double)rbuf[w];
        atomicAdd(&g_loss_acc, s);
    }
}

// --- finalize: loss = COMMITMENT_COST * mean ---------------------------------
__global__ void vq_final_kernel(float* loss_out, int numel) {
    loss_out[0] = (float)(0.25 * g_loss_acc / (double)numel);
}

// ----------------------------------------------------------------------------
extern "C" void kernel_launch(void* const* d_in, const int* in_sizes, int n_in,
                              void* d_out, int out_size)
{
    const float* X = (const float*)d_in[0];
    const float* E = (const float*)d_in[1];
    const int D = DDIM;
    const int K = in_sizes[1] / D;     // 1024
    const int N = in_sizes[0] / D;     // 262144

    float* out    = (float*)d_out;
    float* q      = out;
    float* loss_p = out + (size_t)N * D;
    float* idx_p  = out + (size_t)N * D + 1;

    const size_t smem_bytes =
        (2 * DDIM * XS_STRIDE + MTILE) * sizeof(float) + MTILE * sizeof(int);

    static bool attr_set = false;
    if (!attr_set) {
        cudaFuncSetAttribute(vq_main_kernel,
                             cudaFuncAttributeMaxDynamicSharedMemorySize,
                             (int)smem_bytes);
        attr_set = true;
    }

    vq_prep_kernel<<<(K + 255) / 256, 256>>>(E, K);
    vq_main_kernel<<<N / MTILE, THREADS, smem_bytes>>>(X, E, q, idx_p, K);
    vq_final_kernel<<<1, 1>>>(loss_p, N * D);
}

// round 3
// speedup vs baseline: 2.1839x; 2.1839x over previous
#include <cuda_runtime.h>
#include <cuda_bf16.h>
#include <cstdint>

// ----------------------------------------------------------------------------
// VQ via legacy tensor-core mma.sync (bf16 hi/lo 4-product, fp32 accum)
//   dist GEMM + argmin + gather + loss, fused.
// inputs : d_in[0] = X [N=262144, D=128] fp32 ; d_in[1] = E [128, 1024] fp32
// outputs: d_out = [ quantized (N*D) | loss (1) | indices-as-float (N) ]
// ----------------------------------------------------------------------------

#define KCODES  1024
#define DDIM    128
#define MTILE   128
#define NCHUNK  128
#define NCHUNKS 8
#define THREADS 256

#define XSTRIDE 132            // fp32 X tile row stride (floats)
#define BSTRIDE 288            // E chunk row stride (bytes) = 144 bf16, 16B-mult

// SMEM layout (bytes)
#define SM_X    0                                   // 128*132*4 = 67584
#define SM_B    67584                               // 2 bufs * 2 halves * 36864 = 147456
#define SM_ESQ  (67584 + 147456)                    // 4096
#define SM_XSQ  (SM_ESQ + 4096)                     // 512
#define SM_IDX  (SM_XSQ + 512)                      // 512
#define SM_TOTAL (SM_IDX + 512)                     // 220160

#define BHALF   36864                               // 128 * 288
#define BBUF    (2 * BHALF)

// scratch globals (no cudaMalloc allowed)
__device__ double g_loss_acc;
__device__ __align__(16) float         g_esq[KCODES];
__device__ __align__(16) __nv_bfloat16 g_ET_hi[KCODES * DDIM];   // [k][d]
__device__ __align__(16) __nv_bfloat16 g_ET_lo[KCODES * DDIM];
__device__ __align__(16) float         g_ET_f32[KCODES * DDIM];

// ---- helpers ----------------------------------------------------------------
__device__ __forceinline__ uint32_t smem_u32(const void* p) {
    uint32_t a;
    asm("{ .reg .u64 t; cvta.to.shared.u64 t, %1; cvt.u32.u64 %0, t; }"
        : "=r"(a) : "l"(p));
    return a;
}
__device__ __forceinline__ void cp_async16(uint32_t dst, const void* src) {
    asm volatile("cp.async.cg.shared.global [%0], [%1], 16;"
                 :: "r"(dst), "l"(src) : "memory");
}
__device__ __forceinline__ void cp_commit() {
    asm volatile("cp.async.commit_group;" ::: "memory");
}
template <int N> __device__ __forceinline__ void cp_wait() {
    asm volatile("cp.async.wait_group %0;" :: "n"(N) : "memory");
}
__device__ __forceinline__ void mma16816(float* d, uint32_t a0, uint32_t a1,
                                         uint32_t a2, uint32_t a3,
                                         uint32_t b0, uint32_t b1) {
    asm volatile(
        "mma.sync.aligned.m16n8k16.row.col.f32.bf16.bf16.f32 "
        "{%0,%1,%2,%3}, {%4,%5,%6,%7}, {%8,%9}, {%0,%1,%2,%3};"
        : "+f"(d[0]), "+f"(d[1]), "+f"(d[2]), "+f"(d[3])
        : "r"(a0), "r"(a1), "r"(a2), "r"(a3), "r"(b0), "r"(b1));
}
__device__ __forceinline__ uint32_t pack_bf2(float x, float y) {
    __nv_bfloat162 v = __halves2bfloat162(__float2bfloat16(x), __float2bfloat16(y));
    return *(uint32_t*)&v;
}

// ---- prep: esq, E transpose + hi/lo split, fp32 transpose -------------------
__global__ void vq_prep_kernel(const float* __restrict__ E) {
    int k = blockIdx.x * blockDim.x + threadIdx.x;
    if (k == 0) g_loss_acc = 0.0;
    if (k >= KCODES) return;
    float s = 0.f;
#pragma unroll 8
    for (int d = 0; d < DDIM; ++d) {
        float e = E[(size_t)d * KCODES + k];
        s = fmaf(e, e, s);
        __nv_bfloat16 hi = __float2bfloat16(e);
        __nv_bfloat16 lo = __float2bfloat16(e - __bfloat162float(hi));
        g_ET_hi[k * DDIM + d]  = hi;
        g_ET_lo[k * DDIM + d]  = lo;
        g_ET_f32[k * DDIM + d] = e;
    }
    g_esq[k] = s;
}

// ---- issue cp.async for one E chunk (hi+lo) into buffer buf -----------------
__device__ __forceinline__ void issue_B(char* smem, int buf, int c0, int t) {
    uint32_t base = smem_u32(smem + SM_B) + buf * BBUF;
#pragma unroll
    for (int j = 0; j < 16; ++j) {                 // 4096 ops / 256 threads
        int idx  = t + j * THREADS;
        int half = idx >> 11;                      // 0=hi, 1=lo
        int r    = (idx >> 4) & 127;
        int seg  = idx & 15;
        const __nv_bfloat16* src =
            (half ? g_ET_lo : g_ET_hi) + (size_t)(c0 + r) * DDIM + seg * 8;
        cp_async16(base + half * BHALF + r * BSTRIDE + seg * 16, src);
    }
    cp_commit();
}

// ---- main fused kernel ------------------------------------------------------
__global__ __launch_bounds__(THREADS, 1) void vq_main_kernel(
    const float* __restrict__ X, float* __restrict__ q_out, float* __restrict__ idx_out)
{
    extern __shared__ char smem[];
    float* Xs    = (float*)(smem + SM_X);
    float* esq_s = (float*)(smem + SM_ESQ);
    float* xsq_s = (float*)(smem + SM_XSQ);
    int*   idx_s = (int*)(smem + SM_IDX);

    const int t    = threadIdx.x;
    const int w    = t >> 5;
    const int lane = t & 31;
    const int g    = lane >> 2;          // group id (row within 8)
    const int q    = (lane & 3) << 1;    // col pair offset
    const int rowBase = blockIdx.x * MTILE;

    // prefetch first E chunk immediately
    issue_B(smem, 0, 0, t);

    // esq -> SMEM
    for (int i = t; i < KCODES; i += THREADS) esq_s[i] = g_esq[i];

    // X tile fp32 -> SMEM (coalesced)
    const float4* X4 = (const float4*)(X + (size_t)rowBase * DDIM);
#pragma unroll
    for (int i = 0; i < 16; ++i) {
        int idx = t + i * THREADS;                 // 0..4095 float4
        int row = idx >> 5;
        int c4  = idx & 31;
        *(float4*)&Xs[row * XSTRIDE + c4 * 4] = X4[idx];
    }
    __syncthreads();

    // per-row ||x||^2 (sequential fmaf, same order as round-1 reference match)
    if (t < MTILE) {
        float s = 0.f;
#pragma unroll 8
        for (int d = 0; d < DDIM; ++d) {
            float x = Xs[t * XSTRIDE + d];
            s = fmaf(x, x, s);
        }
        xsq_s[t] = s;
    }

    // build A fragments (hi/lo bf16) in registers, reused for all chunks
    const int r0 = 16 * w + g;           // rowA
    const int r1 = r0 + 8;               // rowB
    uint32_t a_hi[8][4], a_lo[8][4];
#pragma unroll
    for (int ks = 0; ks < 8; ++ks) {
        int k0 = ks * 16;
        float2 f0 = *(const float2*)&Xs[r0 * XSTRIDE + k0 + q];
        float2 f1 = *(const float2*)&Xs[r1 * XSTRIDE + k0 + q];
        float2 f2 = *(const float2*)&Xs[r0 * XSTRIDE + k0 + q + 8];
        float2 f3 = *(const float2*)&Xs[r1 * XSTRIDE + k0 + q + 8];
        a_hi[ks][0] = pack_bf2(f0.x, f0.y);
        a_hi[ks][1] = pack_bf2(f1.x, f1.y);
        a_hi[ks][2] = pack_bf2(f2.x, f2.y);
        a_hi[ks][3] = pack_bf2(f3.x, f3.y);
        float h;
        h = __bfloat162float(__float2bfloat16(f0.x));
        float l0x = f0.x - h;
        h = __bfloat162float(__float2bfloat16(f0.y));
        float l0y = f0.y - h;
        h = __bfloat162float(__float2bfloat16(f1.x));
        float l1x = f1.x - h;
        h = __bfloat162float(__float2bfloat16(f1.y));
        float l1y = f1.y - h;
        h = __bfloat162float(__float2bfloat16(f2.x));
        float l2x = f2.x - h;
        h = __bfloat162float(__float2bfloat16(f2.y));
        float l2y = f2.y - h;
        h = __bfloat162float(__float2bfloat16(f3.x));
        float l3x = f3.x - h;
        h = __bfloat162float(__float2bfloat16(f3.y));
        float l3y = f3.y - h;
        a_lo[ks][0] = pack_bf2(l0x, l0y);
        a_lo[ks][1] = pack_bf2(l1x, l1y);
        a_lo[ks][2] = pack_bf2(l2x, l2y);
        a_lo[ks][3] = pack_bf2(l3x, l3y);
    }
    __syncthreads();
    const float xsqA = xsq_s[r0];
    const float xsqB = xsq_s[r1];

    float mvA = 3.402823466e38f, mvB = 3.402823466e38f;
    int   miA = 0, miB = 0;

    for (int ch = 0; ch < NCHUNKS; ++ch) {
        const int buf = ch & 1;
        if (ch + 1 < NCHUNKS) {
            issue_B(smem, (ch + 1) & 1, (ch + 1) * NCHUNK, t);
            cp_wait<1>();
        } else {
            cp_wait<0>();
        }
        __syncthreads();

        const char* Bh = smem + SM_B + buf * BBUF;
        const char* Bl = Bh + BHALF;

        float acc[16][4];
#pragma unroll
        for (int nt = 0; nt < 16; ++nt) {
            acc[nt][0] = 0.f; acc[nt][1] = 0.f; acc[nt][2] = 0.f; acc[nt][3] = 0.f;
        }

#pragma unroll
        for (int ks = 0; ks < 8; ++ks) {
            const uint32_t ah0 = a_hi[ks][0], ah1 = a_hi[ks][1];
            const uint32_t ah2 = a_hi[ks][2], ah3 = a_hi[ks][3];
            const uint32_t al0 = a_lo[ks][0], al1 = a_lo[ks][1];
            const uint32_t al2 = a_lo[ks][2], al3 = a_lo[ks][3];
            const int koff0 = (ks * 16 + q) * 2;
            const int koff1 = (ks * 16 + q + 8) * 2;
#pragma unroll
            for (int nt = 0; nt < 16; ++nt) {
                const char* rowh = Bh + (nt * 8 + g) * BSTRIDE;
                const char* rowl = Bl + (nt * 8 + g) * BSTRIDE;
                uint32_t bh0 = *(const uint32_t*)(rowh + koff0);
                uint32_t bh1 = *(const uint32_t*)(rowh + koff1);
                uint32_t bl0 = *(const uint32_t*)(rowl + koff0);
                uint32_t bl1 = *(const uint32_t*)(rowl + koff1);
                mma16816(acc[nt], ah0, ah1, ah2, ah3, bh0, bh1);
                mma16816(acc[nt], ah0, ah1, ah2, ah3, bl0, bl1);
                mma16816(acc[nt], al0, al1, al2, al3, bh0, bh1);
                mma16816(acc[nt], al0, al1, al2, al3, bl0, bl1);
            }
        }

        // fold argmin; replicate reference rounding exactly
        const int cbase = ch * NCHUNK;
#pragma unroll
        for (int nt = 0; nt < 16; ++nt) {
            int cA = cbase + nt * 8 + q;
            float2 e2 = *(const float2*)&esq_s[cA];
            float m, tt, dd;
            m = __fmul_rn(2.f, acc[nt][0]); tt = __fadd_rn(xsqA, -m); dd = __fadd_rn(tt, e2.x);
            if (dd < mvA) { mvA = dd; miA = cA; }
            m = __fmul_rn(2.f, acc[nt][1]); tt = __fadd_rn(xsqA, -m); dd = __fadd_rn(tt, e2.y);
            if (dd < mvA) { mvA = dd; miA = cA + 1; }
            m = __fmul_rn(2.f, acc[nt][2]); tt = __fadd_rn(xsqB, -m); dd = __fadd_rn(tt, e2.x);
            if (dd < mvB) { mvB = dd; miB = cA; }
            m = __fmul_rn(2.f, acc[nt][3]); tt = __fadd_rn(xsqB, -m); dd = __fadd_rn(tt, e2.y);
            if (dd < mvB) { mvB = dd; miB = cA + 1; }
        }
        __syncthreads();   // all warps done reading this buffer before reuse
    }

    // quad reduction (lanes sharing a row differ in bits 0-1)
#pragma unroll
    for (int off = 1; off <= 2; off <<= 1) {
        float ov = __shfl_xor_sync(0xffffffffu, mvA, off);
        int   oi = __shfl_xor_sync(0xffffffffu, miA, off);
        if (ov < mvA || (ov == mvA && oi < miA)) { mvA = ov; miA = oi; }
        ov = __shfl_xor_sync(0xffffffffu, mvB, off);
        oi = __shfl_xor_sync(0xffffffffu, miB, off);
        if (ov < mvB || (ov == mvB && oi < miB)) { mvB = ov; miB = oi; }
    }
    if ((lane & 3) == 0) {
        idx_s[r0] = miA;
        idx_s[r1] = miB;
        idx_out[rowBase + r0] = (float)miA;
        idx_out[rowBase + r1] = (float)miB;
    }
    __syncthreads();

    // gather winner (coalesced, code-major fp32), write quantized, loss
    float lsum = 0.f;
    const int d = t & 127, half = t >> 7;
    for (int rr = half; rr < MTILE; rr += 2) {
        int bi = idx_s[rr];
        float e = __ldg(&g_ET_f32[(size_t)bi * DDIM + d]);
        float x = Xs[rr * XSTRIDE + d];
        q_out[(size_t)(rowBase + rr) * DDIM + d] = e;
        float df = e - x;
        lsum = fmaf(df, df, lsum);
    }
#pragma unroll
    for (int o = 16; o > 0; o >>= 1) lsum += __shfl_xor_sync(0xffffffffu, lsum, o);
    __syncthreads();
    float* rbuf = esq_s;   // esq no longer needed
    if ((t & 31) == 0) rbuf[t >> 5] = lsum;
    __syncthreads();
    if (t == 0) {
        double s = 0.0;
        for (int ww = 0; ww < THREADS / 32; ++ww) s += (double)rbuf[ww];
        atomicAdd(&g_loss_acc, s);
    }
}

// ---- finalize ---------------------------------------------------------------
__global__ void vq_final_kernel(float* loss_out, int numel) {
    loss_out[0] = (float)(0.25 * g_loss_acc / (double)numel);
}

// ----------------------------------------------------------------------------
extern "C" void kernel_launch(void* const* d_in, const int* in_sizes, int n_in,
                              void* d_out, int out_size)
{
    const float* X = (const float*)d_in[0];
    const float* E = (const float*)d_in[1];
    const int N = in_sizes[0] / DDIM;     // 262144

    float* out    = (float*)d_out;
    float* q      = out;
    float* loss_p = out + (size_t)N * DDIM;
    float* idx_p  = out + (size_t)N * DDIM + 1;

    static bool attr_set = false;
    if (!attr_set) {
        cudaFuncSetAttribute(vq_main_kernel,
                             cudaFuncAttributeMaxDynamicSharedMemorySize, SM_TOTAL);
        attr_set = true;
    }

    vq_prep_kernel<<<4, 256>>>(E);
    vq_main_kernel<<<N / MTILE, THREADS, SM_TOTAL>>>(X, q, idx_p);
    vq_final_kernel<<<1, 1>>>(loss_p, N * DDIM);
}